// round 2
// baseline (speedup 1.0000x reference)
#include <cuda_runtime.h>
#include <math.h>

// Problem constants
static constexpr int NB  = 2;
static constexpr int NL  = 1024;
static constexpr int NH  = 64;
static constexpr int NV  = 32000;
static constexpr int NT  = NB * NL;      // 2048 tokens
static constexpr int KA  = 448;          // 64 freq + 64 cos + 64 sin + 256 hidden
static constexpr int NT2 = 2 * NT;       // duplicated-A row stride (4096)

// Scratch (device globals: allocation-free)
__device__ float g_At2[KA * NT2];        // K-major token features, each value DUPLICATED:
                                         //   g_At2[k][2t] == g_At2[k][2t+1] == A[k][t]
__device__ float g_Bv[192 * NV];         // K-major packed vocab features (192 x 32000)
__device__ float g_v2[NV];
__device__ float g_f2[NT];
__device__ float g_lamp[NT];

__device__ __forceinline__ float gelu_exact(float x) {
    return 0.5f * x * (1.0f + erff(x * 0.7071067811865476f));
}

__device__ __forceinline__ void fma2(unsigned long long& d,
                                     unsigned long long a,
                                     unsigned long long b) {
    asm("fma.rn.f32x2 %0, %1, %2, %0;" : "+l"(d) : "l"(a), "l"(b));
}

__device__ __forceinline__ float2 unpack2(unsigned long long v) {
    float2 f;
    asm("mov.b64 {%0, %1}, %2;" : "=f"(f.x), "=f"(f.y) : "l"(v));
    return f;
}

// ---------------------------------------------------------------------------
// Token prep: 4 tokens per block, 256 threads. Writes duplicated A rows.
//   rows [0,64)    = freqs (raw)
//   rows [64,128)  = cos(phase) * (0.5/64) * lamp
//   rows [128,192) = sin(phase) * (0.5/64) * lamp
//   rows [192,448) = 0.1 * x_final
// ---------------------------------------------------------------------------
__global__ void token_prep(const float* __restrict__ wave,
                           const float* __restrict__ W0, const float* __restrict__ b0,
                           const float* __restrict__ W1, const float* __restrict__ b1,
                           const float* __restrict__ W2, const float* __restrict__ b2,
                           const float* __restrict__ rw)
{
    __shared__ float sw[4][192];
    __shared__ float sx[4][256];
    __shared__ float sy[4][256];
    __shared__ float slamp[4];

    const int t0 = blockIdx.x * 4;
    const int j  = threadIdx.x;

    for (int i = j; i < 4 * 192; i += 256) {
        int tok = i / 192, kk = i % 192;
        sw[tok][kk] = wave[(size_t)(t0 + tok) * 192 + kk];
    }
    __syncthreads();

    if (j < 8) {
        int tok = j & 3;
        if (j < 4) {
            float s = 0.f;
            for (int h = 0; h < NH; h++) { float f = sw[tok][h]; s += f * f; }
            g_f2[t0 + tok] = s;
        } else {
            float s = 0.f;
            for (int h = 0; h < NH; h++) s += sw[tok][64 + h];
            float l = log1pf(s);
            slamp[tok] = l;
            g_lamp[t0 + tok] = l;
        }
    }

    // layer 0: 192 -> 256
    float acc0 = 0.f, acc1 = 0.f, acc2 = 0.f, acc3 = 0.f;
    float bb = b0[j];
    for (int k = 0; k < 192; k++) {
        float w = W0[k * 256 + j];
        acc0 = fmaf(sw[0][k], w, acc0);
        acc1 = fmaf(sw[1][k], w, acc1);
        acc2 = fmaf(sw[2][k], w, acc2);
        acc3 = fmaf(sw[3][k], w, acc3);
    }
    __syncthreads();
    sx[0][j] = gelu_exact(acc0 + bb);
    sx[1][j] = gelu_exact(acc1 + bb);
    sx[2][j] = gelu_exact(acc2 + bb);
    sx[3][j] = gelu_exact(acc3 + bb);
    __syncthreads();

    // layer 1
    bb = b1[j];
    float r1 = rw[1];
    acc0 = acc1 = acc2 = acc3 = 0.f;
    for (int k = 0; k < 256; k++) {
        float w = W1[k * 256 + j];
        acc0 = fmaf(sx[0][k], w, acc0);
        acc1 = fmaf(sx[1][k], w, acc1);
        acc2 = fmaf(sx[2][k], w, acc2);
        acc3 = fmaf(sx[3][k], w, acc3);
    }
    sy[0][j] = gelu_exact(acc0 + bb) + r1 * sx[0][j];
    sy[1][j] = gelu_exact(acc1 + bb) + r1 * sx[1][j];
    sy[2][j] = gelu_exact(acc2 + bb) + r1 * sx[2][j];
    sy[3][j] = gelu_exact(acc3 + bb) + r1 * sx[3][j];
    __syncthreads();

    // layer 2
    bb = b2[j];
    float r2 = rw[2];
    acc0 = acc1 = acc2 = acc3 = 0.f;
    for (int k = 0; k < 256; k++) {
        float w = W2[k * 256 + j];
        acc0 = fmaf(sy[0][k], w, acc0);
        acc1 = fmaf(sy[1][k], w, acc1);
        acc2 = fmaf(sy[2][k], w, acc2);
        acc3 = fmaf(sy[3][k], w, acc3);
    }
    {
        float z[4];
        z[0] = 0.1f * (gelu_exact(acc0 + bb) + r2 * sy[0][j]);
        z[1] = 0.1f * (gelu_exact(acc1 + bb) + r2 * sy[1][j]);
        z[2] = 0.1f * (gelu_exact(acc2 + bb) + r2 * sy[2][j]);
        z[3] = 0.1f * (gelu_exact(acc3 + bb) + r2 * sy[3][j]);
        #pragma unroll
        for (int i = 0; i < 4; i++) {
            float2 d; d.x = z[i]; d.y = z[i];
            *(float2*)&g_At2[(size_t)(192 + j) * NT2 + 2 * (t0 + i)] = d;
        }
    }

    // freq + trig rows: thread j -> token i = j>>6, h = j&63
    {
        int i = j >> 6, h = j & 63;
        float f  = sw[i][h];
        float ph = sw[i][128 + h];
        float sc = 0.0078125f * slamp[i];     // (0.5/64) * log1p(amp_energy)
        float sn, cs;
        sincosf(ph, &sn, &cs);
        float2 d;
        d.x = d.y = f;
        *(float2*)&g_At2[(size_t)h          * NT2 + 2 * (t0 + i)] = d;
        d.x = d.y = cs * sc;
        *(float2*)&g_At2[(size_t)(64 + h)   * NT2 + 2 * (t0 + i)] = d;
        d.x = d.y = sn * sc;
        *(float2*)&g_At2[(size_t)(128 + h)  * NT2 + 2 * (t0 + i)] = d;
    }
}

// ---------------------------------------------------------------------------
// Vocab prep
// ---------------------------------------------------------------------------
__global__ void vocab_v2_kernel(const float* __restrict__ vf)
{
    int v = blockIdx.x * 256 + threadIdx.x;
    if (v >= NV) return;
    const float* r = vf + (size_t)v * NH;
    float s = 0.f;
    #pragma unroll
    for (int h = 0; h < NH; h++) s = fmaf(r[h], r[h], s);
    g_v2[v] = s;
}

__global__ void vocab_pack(const float* __restrict__ vf, const float* __restrict__ vp)
{
    __shared__ float tf[32][33], tc[32][33], ts[32][33];
    const int v0 = blockIdx.x * 32;
    const int h0 = blockIdx.y * 32;
    const int tx = threadIdx.x, ty = threadIdx.y;   // (32, 8)
    #pragma unroll
    for (int r = 0; r < 4; r++) {
        int vv = v0 + ty + r * 8, hh = h0 + tx;
        float f = vf[(size_t)vv * NH + hh];
        float p = vp[(size_t)vv * NH + hh];
        float sn, cs; sincosf(p, &sn, &cs);
        tf[ty + r * 8][tx] = f;
        tc[ty + r * 8][tx] = cs;
        ts[ty + r * 8][tx] = sn;
    }
    __syncthreads();
    #pragma unroll
    for (int r = 0; r < 4; r++) {
        int hh = h0 + ty + r * 8, vv = v0 + tx;
        g_Bv[(size_t)hh         * NV + vv] = tf[tx][ty + r * 8];
        g_Bv[(size_t)(64 + hh)  * NV + vv] = tc[tx][ty + r * 8];
        g_Bv[(size_t)(128 + hh) * NV + vv] = ts[tx][ty + r * 8];
    }
}

// ---------------------------------------------------------------------------
// Main fused GEMM with packed f32x2 FFMA, double-buffered smem.
// 64x128 tile, KC=16, 256 threads, 8 rows x 4 cols (= 2 f32x2) per thread.
// accC over K [0,64) (cross), accT over K [64,448) (coherence+synthesis).
// ---------------------------------------------------------------------------
static constexpr int TM = 64;
static constexpr int TN = 128;
static constexpr int KC = 16;

__global__ void __launch_bounds__(256, 2)
spectral_gemm(const float* __restrict__ Wv, const float* __restrict__ bv,
              float* __restrict__ out)
{
    __shared__ float AsD[2][KC][2 * TM];   // duplicated A: 2*64 floats per k row
    __shared__ float Bs [2][KC][TN];

    const int v0 = blockIdx.x * TN;
    const int t0 = blockIdx.y * TM;
    const int tid = threadIdx.x;
    const int col0 = (tid & 31) * 4;   // 0..124  (4 output cols = 2 f32x2)
    const int row0 = (tid >> 5) * 8;   // 0..56
    const int lk  = tid >> 4;          // 0..15
    const int lcA = (tid & 15) * 8;    // 0..120 (duplicated row: 16 thr x 8 floats = 128)
    const int lcB = (tid & 15) * 4;    // 0..60

    unsigned long long accC[8][2];
    unsigned long long accT[8][2];
    const unsigned long long Z = 0ull;
    #pragma unroll
    for (int r = 0; r < 8; r++) { accC[r][0] = Z; accC[r][1] = Z; accT[r][0] = Z; accT[r][1] = Z; }

#define LOAD_TILE(K0, BUF) {                                                         \
        int kk = (K0) + lk;                                                          \
        const float* ar = g_At2 + (size_t)kk * NT2 + 2 * t0 + lcA;                   \
        *(float4*)&AsD[BUF][lk][lcA]     = *(const float4*)(ar);                     \
        *(float4*)&AsD[BUF][lk][lcA + 4] = *(const float4*)(ar + 4);                 \
        const float* br = (kk < 192) ? (g_Bv + (size_t)kk * NV)                      \
                                     : (Wv + (size_t)(kk - 192) * NV);               \
        *(float4*)&Bs[BUF][lk][lcB]      = *(const float4*)(br + v0 + lcB);          \
        *(float4*)&Bs[BUF][lk][lcB + 64] = *(const float4*)(br + v0 + lcB + 64);     \
    }

#define MMA_STEP(BUF, ACC) {                                                         \
        _Pragma("unroll")                                                            \
        for (int k = 0; k < KC; k++) {                                               \
            ulonglong2 bq = *(const ulonglong2*)&Bs[BUF][k][col0];                   \
            ulonglong2 a0 = *(const ulonglong2*)&AsD[BUF][k][2 * row0];              \
            ulonglong2 a1 = *(const ulonglong2*)&AsD[BUF][k][2 * row0 + 4];          \
            ulonglong2 a2 = *(const ulonglong2*)&AsD[BUF][k][2 * row0 + 8];          \
            ulonglong2 a3 = *(const ulonglong2*)&AsD[BUF][k][2 * row0 + 12];         \
            unsigned long long av[8] = {a0.x, a0.y, a1.x, a1.y,                      \
                                        a2.x, a2.y, a3.x, a3.y};                     \
            _Pragma("unroll")                                                        \
            for (int r = 0; r < 8; r++) {                                            \
                fma2(ACC[r][0], av[r], bq.x);                                        \
                fma2(ACC[r][1], av[r], bq.y);                                        \
            }                                                                        \
        }                                                                            \
    }

    LOAD_TILE(0, 0);
    __syncthreads();
    #pragma unroll 1
    for (int ch = 0; ch < 28; ch++) {
        int cur = ch & 1;
        if (ch < 27) LOAD_TILE((ch + 1) * KC, cur ^ 1);
        if (ch < 4) { MMA_STEP(cur, accC); }
        else        { MMA_STEP(cur, accT); }
        __syncthreads();
    }
#undef LOAD_TILE
#undef MMA_STEP

    // Epilogue
    float f2r[8], lam[8];
    #pragma unroll
    for (int r = 0; r < 8; r++) {
        f2r[r] = g_f2[t0 + row0 + r];
        lam[r] = g_lamp[t0 + row0 + r];
    }
    float v2c[4], bvc[4];
    #pragma unroll
    for (int c = 0; c < 4; c++) {
        v2c[c] = g_v2[v0 + col0 + c];
        bvc[c] = 0.1f * bv[v0 + col0 + c];
    }
    #pragma unroll
    for (int r = 0; r < 8; r++) {
        float2 c01 = unpack2(accC[r][0]);
        float2 c23 = unpack2(accC[r][1]);
        float2 t01 = unpack2(accT[r][0]);
        float2 t23 = unpack2(accT[r][1]);
        float cc[4] = {c01.x, c01.y, c23.x, c23.y};
        float tt[4] = {t01.x, t01.y, t23.x, t23.y};
        float4 o;
        float* po = (float*)&o;
        #pragma unroll
        for (int c = 0; c < 4; c++) {
            float d2 = f2r[r] + v2c[c] - 2.0f * cc[c];
            po[c] = tt[c] - sqrtf(fmaxf(d2, 0.0f)) * lam[r] + bvc[c];
        }
        *(float4*)(out + (size_t)(t0 + row0 + r) * NV + v0 + col0) = o;
    }
}

// ---------------------------------------------------------------------------
extern "C" void kernel_launch(void* const* d_in, const int* in_sizes, int n_in,
                              void* d_out, int out_size)
{
    const float* wave = (const float*)d_in[0];   // (2,1024,192)
    const float* vf   = (const float*)d_in[1];   // (32000,64)
    const float* vp   = (const float*)d_in[2];   // (32000,64)
    const float* W0   = (const float*)d_in[3];   // (192,256)
    const float* b0   = (const float*)d_in[4];
    const float* W1   = (const float*)d_in[5];   // (256,256)
    const float* b1   = (const float*)d_in[6];
    const float* W2   = (const float*)d_in[7];   // (256,256)
    const float* b2   = (const float*)d_in[8];
    const float* Wv   = (const float*)d_in[9];   // (256,32000) — K-major for GEMM
    const float* bv   = (const float*)d_in[10];  // (32000,)
    const float* rw   = (const float*)d_in[11];  // (3,)
    float* out = (float*)d_out;

    token_prep<<<NT / 4, 256>>>(wave, W0, b0, W1, b1, W2, b2, rw);
    vocab_v2_kernel<<<(NV + 255) / 256, 256>>>(vf);
    vocab_pack<<<dim3(NV / 32, NH / 32), dim3(32, 8)>>>(vf, vp);
    spectral_gemm<<<dim3(NV / TN, NT / TM), 256>>>(Wv, bv, out);
}

// round 5
// speedup vs baseline: 3.0959x; 3.0959x over previous
#include <cuda_runtime.h>
#include <cuda_bf16.h>
#include <math.h>
#include <stdint.h>

// ---------------------------------------------------------------------------
// Problem constants
// ---------------------------------------------------------------------------
static constexpr int NT = 2048;      // tokens (B*L)
static constexpr int NH = 64;
static constexpr int NV = 32000;
static constexpr int KK = 448;       // 64 freq + 64 cos + 64 sin + 256 hidden

// GEMM tiling (mma.sync path)
static constexpr int CTA_M = 128;
static constexpr int CTA_N = 64;
static constexpr int KC    = 64;               // K per chunk
static constexpr int NCHUNK = KK / KC;         // 7

// SMEM stage layout (bytes). Rows are 128B (64 bf16), SW128-swizzled.
static constexpr int AH_BYTES = CTA_M * KC * 2;   // 16384
static constexpr int BH_BYTES = CTA_N * KC * 2;   // 8192
static constexpr int OFF_AH = 0;
static constexpr int OFF_AL = AH_BYTES;                    // 16384
static constexpr int OFF_BH = 2 * AH_BYTES;                // 32768
static constexpr int OFF_BL = 2 * AH_BYTES + BH_BYTES;     // 40960
static constexpr int STAGE_BYTES = 2 * AH_BYTES + 2 * BH_BYTES;  // 49152
static constexpr int SMEM_TOTAL = 2 * STAGE_BYTES;               // 98304

// ---------------------------------------------------------------------------
// Device scratch (allocation-free)
// ---------------------------------------------------------------------------
__device__ __nv_bfloat16 g_Ah[NT * KK];
__device__ __nv_bfloat16 g_Al[NT * KK];
__device__ __nv_bfloat16 g_Bh[(size_t)NV * KK];
__device__ __nv_bfloat16 g_Bl[(size_t)NV * KK];
__device__ float g_v2[NV];
__device__ float g_f2[NT];
__device__ float g_lamp[NT];

// ---------------------------------------------------------------------------
// Helpers
// ---------------------------------------------------------------------------
__device__ __forceinline__ uint32_t smem_u32(const void* p) {
    uint32_t a;
    asm("{ .reg .u64 t; cvta.to.shared.u64 t, %1; cvt.u32.u64 %0, t; }" : "=r"(a) : "l"(p));
    return a;
}
#define SW128(off) ((off) ^ (((off) >> 3) & 0x70))

__device__ __forceinline__ void cpa16(uint32_t saddr, const void* gaddr) {
    asm volatile("cp.async.cg.shared.global [%0], [%1], 16;" :: "r"(saddr), "l"(gaddr));
}
#define CPA_COMMIT() asm volatile("cp.async.commit_group;" ::: "memory")
#define CPA_WAIT1()  asm volatile("cp.async.wait_group 1;" ::: "memory")
#define CPA_WAIT0()  asm volatile("cp.async.wait_group 0;" ::: "memory")

#define LDSM_X4(r, addr) \
    asm volatile("ldmatrix.sync.aligned.m8n8.x4.shared.b16 {%0,%1,%2,%3}, [%4];" \
        : "=r"((r)[0]), "=r"((r)[1]), "=r"((r)[2]), "=r"((r)[3]) : "r"(addr))

#define MMA16816(C, A, B0, B1) \
    asm volatile("mma.sync.aligned.m16n8k16.row.col.f32.bf16.bf16.f32 " \
        "{%0,%1,%2,%3}, {%4,%5,%6,%7}, {%8,%9}, {%0,%1,%2,%3};" \
        : "+f"((C)[0]), "+f"((C)[1]), "+f"((C)[2]), "+f"((C)[3]) \
        : "r"((A)[0]), "r"((A)[1]), "r"((A)[2]), "r"((A)[3]), "r"(B0), "r"(B1))

__device__ __forceinline__ float gelu_exact(float x) {
    return 0.5f * x * (1.0f + erff(x * 0.7071067811865476f));
}
__device__ __forceinline__ void split_store(float v, size_t idx,
                                            __nv_bfloat16* hi, __nv_bfloat16* lo) {
    __nv_bfloat16 h = __float2bfloat16(v);
    hi[idx] = h;
    lo[idx] = __float2bfloat16(v - __bfloat162float(h));
}

// ---------------------------------------------------------------------------
// Token prep: 4 tokens / block, 256 threads.  Writes A rows [t][448] hi/lo:
//   cols [0,64)=freq, [64,128)=cos(ph)*sc, [128,192)=sin(ph)*sc, [192,448)=0.1*x
//   sc = (0.5/64) * log1p(sum amps)
// ---------------------------------------------------------------------------
__global__ void token_prep(const float* __restrict__ wave,
                           const float* __restrict__ W0, const float* __restrict__ b0,
                           const float* __restrict__ W1, const float* __restrict__ b1,
                           const float* __restrict__ W2, const float* __restrict__ b2,
                           const float* __restrict__ rw)
{
    __shared__ float sw[4][192];
    __shared__ float sx[4][256];
    __shared__ float sy[4][256];
    __shared__ float slamp[4];

    const int t0 = blockIdx.x * 4;
    const int j  = threadIdx.x;

    for (int i = j; i < 4 * 192; i += 256) {
        int tok = i / 192, kk = i % 192;
        sw[tok][kk] = wave[(size_t)(t0 + tok) * 192 + kk];
    }
    __syncthreads();

    if (j < 8) {
        int tok = j & 3;
        if (j < 4) {
            float s = 0.f;
            for (int h = 0; h < NH; h++) { float f = sw[tok][h]; s += f * f; }
            g_f2[t0 + tok] = s;
        } else {
            float s = 0.f;
            for (int h = 0; h < NH; h++) s += sw[tok][64 + h];
            float l = log1pf(s);
            slamp[tok] = l;
            g_lamp[t0 + tok] = l;
        }
    }

    // layer 0: 192 -> 256
    float acc0 = 0.f, acc1 = 0.f, acc2 = 0.f, acc3 = 0.f;
    float bb = b0[j];
    for (int k = 0; k < 192; k++) {
        float w = W0[k * 256 + j];
        acc0 = fmaf(sw[0][k], w, acc0);
        acc1 = fmaf(sw[1][k], w, acc1);
        acc2 = fmaf(sw[2][k], w, acc2);
        acc3 = fmaf(sw[3][k], w, acc3);
    }
    __syncthreads();
    sx[0][j] = gelu_exact(acc0 + bb);
    sx[1][j] = gelu_exact(acc1 + bb);
    sx[2][j] = gelu_exact(acc2 + bb);
    sx[3][j] = gelu_exact(acc3 + bb);
    __syncthreads();

    bb = b1[j];
    float r1 = rw[1];
    acc0 = acc1 = acc2 = acc3 = 0.f;
    for (int k = 0; k < 256; k++) {
        float w = W1[k * 256 + j];
        acc0 = fmaf(sx[0][k], w, acc0);
        acc1 = fmaf(sx[1][k], w, acc1);
        acc2 = fmaf(sx[2][k], w, acc2);
        acc3 = fmaf(sx[3][k], w, acc3);
    }
    sy[0][j] = gelu_exact(acc0 + bb) + r1 * sx[0][j];
    sy[1][j] = gelu_exact(acc1 + bb) + r1 * sx[1][j];
    sy[2][j] = gelu_exact(acc2 + bb) + r1 * sx[2][j];
    sy[3][j] = gelu_exact(acc3 + bb) + r1 * sx[3][j];
    __syncthreads();

    bb = b2[j];
    float r2 = rw[2];
    acc0 = acc1 = acc2 = acc3 = 0.f;
    for (int k = 0; k < 256; k++) {
        float w = W2[k * 256 + j];
        acc0 = fmaf(sy[0][k], w, acc0);
        acc1 = fmaf(sy[1][k], w, acc1);
        acc2 = fmaf(sy[2][k], w, acc2);
        acc3 = fmaf(sy[3][k], w, acc3);
    }
    {
        float z[4];
        z[0] = 0.1f * (gelu_exact(acc0 + bb) + r2 * sy[0][j]);
        z[1] = 0.1f * (gelu_exact(acc1 + bb) + r2 * sy[1][j]);
        z[2] = 0.1f * (gelu_exact(acc2 + bb) + r2 * sy[2][j]);
        z[3] = 0.1f * (gelu_exact(acc3 + bb) + r2 * sy[3][j]);
        #pragma unroll
        for (int i = 0; i < 4; i++)
            split_store(z[i], (size_t)(t0 + i) * KK + 192 + j, g_Ah, g_Al);
    }

    {
        int i = j >> 6, h = j & 63;
        float f  = sw[i][h];
        float ph = sw[i][128 + h];
        float sc = 0.0078125f * slamp[i];
        float sn, cs;
        sincosf(ph, &sn, &cs);
        size_t base = (size_t)(t0 + i) * KK;
        split_store(f,       base + h,        g_Ah, g_Al);
        split_store(cs * sc, base + 64 + h,   g_Ah, g_Al);
        split_store(sn * sc, base + 128 + h,  g_Ah, g_Al);
    }
}

// ---------------------------------------------------------------------------
// Vocab prep
// ---------------------------------------------------------------------------
__global__ void vocab_v2_kernel(const float* __restrict__ vf)
{
    int v = blockIdx.x * 256 + threadIdx.x;
    if (v >= NV) return;
    const float* r = vf + (size_t)v * NH;
    float s = 0.f;
    #pragma unroll
    for (int h = 0; h < NH; h++) s = fmaf(r[h], r[h], s);
    g_v2[v] = s;
}

// B rows [v][448]: cols [0,64)=vf, [64,128)=cos(vp), [128,192)=sin(vp)
__global__ void vocab_feat(const float* __restrict__ vf, const float* __restrict__ vp)
{
    size_t idx = (size_t)blockIdx.x * 256 + threadIdx.x;   // v*64 + h
    if (idx >= (size_t)NV * NH) return;
    int v = (int)(idx >> 6), h = (int)(idx & 63);
    float f = vf[idx];
    float p = vp[idx];
    float sn, cs;
    sincosf(p, &sn, &cs);
    size_t base = (size_t)v * KK;
    split_store(f,  base + h,       g_Bh, g_Bl);
    split_store(cs, base + 64 + h,  g_Bh, g_Bl);
    split_store(sn, base + 128 + h, g_Bh, g_Bl);
}

// B cols [192,448) = Wv^T (Wv is [256][32000]) via tiled transpose
__global__ void wv_transpose(const float* __restrict__ Wv)
{
    __shared__ float st[32][33];
    const int v0 = blockIdx.x * 32;
    const int k0 = blockIdx.y * 32;
    const int tx = threadIdx.x, ty = threadIdx.y;   // (32, 8)
    #pragma unroll
    for (int r = 0; r < 4; r++)
        st[ty + r * 8][tx] = Wv[(size_t)(k0 + ty + r * 8) * NV + v0 + tx];
    __syncthreads();
    #pragma unroll
    for (int r = 0; r < 4; r++) {
        int v = v0 + ty + r * 8, k = k0 + tx;
        split_store(st[tx][ty + r * 8], (size_t)v * KK + 192 + k, g_Bh, g_Bl);
    }
}

// ---------------------------------------------------------------------------
// Main GEMM on mma.sync.m16n8k16 (bf16 3-product split).
// CTA 128x64, 8 warps (4M x 2N), warp tile 32x32.
// Chunk 0 = cross term; in-register transform after it; chunks 1..6 add the
// linear terms (0.5*coh*lam + 0.1*synth) on top.
// ---------------------------------------------------------------------------
__global__ void __launch_bounds__(256)
spectral_hmma(const float* __restrict__ bv, float* __restrict__ out)
{
    extern __shared__ char smem[];
    const uint32_t sbase = smem_u32(smem);

    const int tid = threadIdx.x;
    const int wid = tid >> 5;
    const int lid = tid & 31;
    const int wm = wid & 3;          // 0..3 -> M offset wm*32
    const int wn = wid >> 2;         // 0..1 -> N offset wn*32
    const int v0 = blockIdx.x * CTA_N;
    const int m0 = blockIdx.y * CTA_M;

    // lane-derived ldmatrix address components
    const int a_row = lid & 15;                       // row within 16-row tile
    const int a_c16 = (lid >> 4) & 1;                 // k half (16B units)
    const int b_row = ((lid >> 4) & 1) * 8 + (lid & 7);
    const int b_c16 = (lid >> 3) & 1;

    float acc[2][4][4];
    #pragma unroll
    for (int mt = 0; mt < 2; mt++)
        #pragma unroll
        for (int nt = 0; nt < 4; nt++)
            #pragma unroll
            for (int e = 0; e < 4; e++) acc[mt][nt][e] = 0.f;

    auto load_stage = [&](int stage, int kc) {
        const uint32_t sb = sbase + stage * STAGE_BYTES;
        // A hi/lo: 128 rows x 128B -> 1024 16B units each
        #pragma unroll
        for (int i = 0; i < 4; i++) {
            int idx = tid + i * 256;
            int r = idx >> 3, u = idx & 7;
            uint32_t so = (uint32_t)(r * 128 + ((u * 16) ^ ((r & 7) << 4)));
            size_t go = (size_t)(m0 + r) * KK + kc + u * 8;
            cpa16(sb + OFF_AH + so, g_Ah + go);
            cpa16(sb + OFF_AL + so, g_Al + go);
        }
        // B hi/lo: 64 rows x 128B -> 512 units each
        #pragma unroll
        for (int i = 0; i < 2; i++) {
            int idx = tid + i * 256;
            int r = idx >> 3, u = idx & 7;
            uint32_t so = (uint32_t)(r * 128 + ((u * 16) ^ ((r & 7) << 4)));
            size_t go = (size_t)(v0 + r) * KK + kc + u * 8;
            cpa16(sb + OFF_BH + so, g_Bh + go);
            cpa16(sb + OFF_BL + so, g_Bl + go);
        }
        CPA_COMMIT();
    };

    load_stage(0, 0);

    #pragma unroll 1
    for (int c = 0; c < NCHUNK; c++) {
        if (c < NCHUNK - 1) { load_stage((c + 1) & 1, (c + 1) * KC); CPA_WAIT1(); }
        else                { CPA_WAIT0(); }
        __syncthreads();

        const uint32_t sb = sbase + (c & 1) * STAGE_BYTES;

        #pragma unroll
        for (int ks = 0; ks < 4; ks++) {
            uint32_t ah[2][4], al[2][4], bh[2][4], bl[2][4];
            #pragma unroll
            for (int mt = 0; mt < 2; mt++) {
                int R = wm * 32 + mt * 16 + a_row;
                uint32_t off = (uint32_t)(R * 128 + ((ks * 32 + a_c16 * 16) ^ ((R & 7) << 4)));
                LDSM_X4(ah[mt], sb + OFF_AH + off);
                LDSM_X4(al[mt], sb + OFF_AL + off);
            }
            #pragma unroll
            for (int ng = 0; ng < 2; ng++) {
                int R = wn * 32 + ng * 16 + b_row;
                uint32_t off = (uint32_t)(R * 128 + ((ks * 32 + b_c16 * 16) ^ ((R & 7) << 4)));
                LDSM_X4(bh[ng], sb + OFF_BH + off);
                LDSM_X4(bl[ng], sb + OFF_BL + off);
            }
            #pragma unroll
            for (int mt = 0; mt < 2; mt++)
                #pragma unroll
                for (int nt = 0; nt < 4; nt++) {
                    int ng = nt >> 1, sub = nt & 1;
                    MMA16816(acc[mt][nt], ah[mt], bh[ng][sub * 2], bh[ng][sub * 2 + 1]);
                    MMA16816(acc[mt][nt], ah[mt], bl[ng][sub * 2], bl[ng][sub * 2 + 1]);
                    MMA16816(acc[mt][nt], al[mt], bh[ng][sub * 2], bh[ng][sub * 2 + 1]);
                }
        }

        if (c == 0) {
            // acc currently = cross = <freq, vocab_freq>.  Transform:
            //   acc <- 0.1*bv[col] - sqrt(max(f2[row]+v2[col]-2*acc, 0))*lam[row]
            #pragma unroll
            for (int mt = 0; mt < 2; mt++) {
                int r0 = m0 + wm * 32 + mt * 16 + (lid >> 2);
                int r1 = r0 + 8;
                float f2a = g_f2[r0],  lma = g_lamp[r0];
                float f2b = g_f2[r1],  lmb = g_lamp[r1];
                #pragma unroll
                for (int nt = 0; nt < 4; nt++) {
                    int c0 = v0 + wn * 32 + (nt >> 1) * 16 + (nt & 1) * 8 + 2 * (lid & 3);
                    float v2x = g_v2[c0],     bvx = 0.1f * bv[c0];
                    float v2y = g_v2[c0 + 1], bvy = 0.1f * bv[c0 + 1];
                    float* a = acc[mt][nt];
                    a[0] = bvx - sqrtf(fmaxf(f2a + v2x - 2.f * a[0], 0.f)) * lma;
                    a[1] = bvy - sqrtf(fmaxf(f2a + v2y - 2.f * a[1], 0.f)) * lma;
                    a[2] = bvx - sqrtf(fmaxf(f2b + v2x - 2.f * a[2], 0.f)) * lmb;
                    a[3] = bvy - sqrtf(fmaxf(f2b + v2y - 2.f * a[3], 0.f)) * lmb;
                }
            }
        }
        __syncthreads();
    }

    // Writeout
    #pragma unroll
    for (int mt = 0; mt < 2; mt++) {
        size_t r0 = (size_t)(m0 + wm * 32 + mt * 16 + (lid >> 2));
        #pragma unroll
        for (int nt = 0; nt < 4; nt++) {
            int c0 = v0 + wn * 32 + (nt >> 1) * 16 + (nt & 1) * 8 + 2 * (lid & 3);
            float2 lo = make_float2(acc[mt][nt][0], acc[mt][nt][1]);
            float2 hi = make_float2(acc[mt][nt][2], acc[mt][nt][3]);
            *(float2*)(out + r0 * NV + c0)       = lo;
            *(float2*)(out + (r0 + 8) * NV + c0) = hi;
        }
    }
}

// ---------------------------------------------------------------------------
extern "C" void kernel_launch(void* const* d_in, const int* in_sizes, int n_in,
                              void* d_out, int out_size)
{
    const float* wave = (const float*)d_in[0];   // (2,1024,192)
    const float* vf   = (const float*)d_in[1];   // (32000,64)
    const float* vp   = (const float*)d_in[2];   // (32000,64)
    const float* W0   = (const float*)d_in[3];   // (192,256)
    const float* b0   = (const float*)d_in[4];
    const float* W1   = (const float*)d_in[5];   // (256,256)
    const float* b1   = (const float*)d_in[6];
    const float* W2   = (const float*)d_in[7];   // (256,256)
    const float* b2   = (const float*)d_in[8];
    const float* Wv   = (const float*)d_in[9];   // (256,32000)
    const float* bv   = (const float*)d_in[10];  // (32000,)
    const float* rw   = (const float*)d_in[11];  // (3,)
    float* out = (float*)d_out;

    cudaFuncSetAttribute(spectral_hmma,
                         cudaFuncAttributeMaxDynamicSharedMemorySize, SMEM_TOTAL);

    token_prep<<<NT / 4, 256>>>(wave, W0, b0, W1, b1, W2, b2, rw);
    vocab_v2_kernel<<<(NV + 255) / 256, 256>>>(vf);
    vocab_feat<<<(int)(((size_t)NV * NH + 255) / 256), 256>>>(vf, vp);
    wv_transpose<<<dim3(NV / 32, 256 / 32), dim3(32, 8)>>>(Wv);
    spectral_hmma<<<dim3(NV / CTA_N, NT / CTA_M), 256, SMEM_TOTAL>>>(bv, out);
}